// round 7
// baseline (speedup 1.0000x reference)
#include <cuda_runtime.h>
#include <cuda_bf16.h>
#include <math.h>
#include <stdint.h>

// ---------------- problem constants ----------------
#define BATCH  32
#define HEADS  12
#define SEQ    512
#define LHALF  256
#define DMODEL 768
#define HH     384          // hidden per direction
#define G4     1536         // 4*HH gates
#define DIN    1536         // 2*DMODEL LSTM input
#define BH     384          // BATCH*HEADS
#define TT     6            // SLIDER
#define EPSV   1e-9f

// ---------------- device scratch (no allocs allowed) ----------------
__device__ int   g_master[BH * 2];
__device__ float g_gatesX[(size_t)BH * TT * 2 * G4];   // 2304 x 3072 (fwd | rev), bias folded
__device__ float g_gtmp[(size_t)2 * BH * G4];          // per-step h @ whh^T
__device__ float g_compose[(size_t)BH * TT * DMODEL];
__device__ float g_lrep[(size_t)BATCH * DMODEL];

// bf16 split operands
__device__ __nv_bfloat16 g_slide_h[(size_t)BH * TT * DIN];
__device__ __nv_bfloat16 g_slide_l[(size_t)BH * TT * DIN];
__device__ __nv_bfloat16 g_wih_h[(size_t)2 * G4 * DIN];   // [3072][1536]
__device__ __nv_bfloat16 g_wih_l[(size_t)2 * G4 * DIN];
__device__ __nv_bfloat16 g_whh_h[(size_t)2 * G4 * HH];    // [2][1536][384]
__device__ __nv_bfloat16 g_whh_l[(size_t)2 * G4 * HH];
__device__ __nv_bfloat16 g_hb_h[(size_t)2 * BH * HH];     // [2][384][384]
__device__ __nv_bfloat16 g_hb_l[(size_t)2 * BH * HH];
__device__ float g_bias[2 * G4];

// grid barrier state (self-resetting; replay-safe)
__device__ unsigned g_bar_cnt;
__device__ unsigned g_bar_gen;

// ---------------- PTX helpers (baseline PTX only) ----------------
__device__ __forceinline__ uint32_t smem_u32(const void* p) {
    uint32_t a;
    asm("{ .reg .u64 t; cvta.to.shared.u64 t, %1; cvt.u32.u64 %0, t; }" : "=r"(a) : "l"(p));
    return a;
}

#define CP_ASYNC16(sm, gm) \
    asm volatile("cp.async.cg.shared.global [%0], [%1], 16;" :: "r"(sm), "l"(gm) : "memory")
#define CP_COMMIT() asm volatile("cp.async.commit_group;" ::: "memory")
#define CP_WAIT0()  asm volatile("cp.async.wait_group 0;" ::: "memory")

#define LDSM_X4(r0, r1, r2, r3, addr) \
    asm volatile("ldmatrix.sync.aligned.m8n8.x4.shared.b16 {%0,%1,%2,%3}, [%4];" \
        : "=r"(r0), "=r"(r1), "=r"(r2), "=r"(r3) : "r"(addr))

#define MMA_BF16(c0, c1, c2, c3, a0, a1, a2, a3, b0, b1) \
    asm volatile("mma.sync.aligned.m16n8k16.row.col.f32.bf16.bf16.f32 " \
        "{%0,%1,%2,%3}, {%4,%5,%6,%7}, {%8,%9}, {%0,%1,%2,%3};" \
        : "+f"(c0), "+f"(c1), "+f"(c2), "+f"(c3) \
        : "r"(a0), "r"(a1), "r"(a2), "r"(a3), "r"(b0), "r"(b1))

// ---------------- helpers ----------------
__device__ __forceinline__ float sigf(float x) { return 1.0f / (1.0f + expf(-x)); }

__device__ __forceinline__ int window_start(int pos) {
    pos = min(max(pos, 1), LHALF - 2);
    int l = TT / 2;
    if (pos - TT / 2 <= 0) l = pos - 1;
    int r = TT - l;
    if (pos + r >= LHALF - 1) l = TT - (LHALF - pos - 2);
    return pos - l;
}

// ---------------- K1: masters ----------------
__global__ void masters_kernel(const float* __restrict__ att, const int* __restrict__ sents) {
    int bid  = blockIdx.x;
    int half = bid & 1;
    int bh   = bid >> 1;
    int b    = bh / HEADS;

    __shared__ unsigned char seps[LHALF];
    __shared__ float rowsum[LHALF];

    int tid = threadIdx.x;
    {
        int j = half * LHALF + tid;
        seps[tid] = (sents[b * SEQ + j] == 102) ? 1 : 0;
    }
    __syncthreads();

    const float* base = att + ((size_t)bh * SEQ + (size_t)half * LHALF) * SEQ + (size_t)half * LHALF;

    int warp = tid >> 5, lane = tid & 31;
    for (int row = warp; row < LHALF; row += 8) {
        const float4* rp4 = (const float4*)(base + (size_t)row * SEQ);
        float s = 0.0f;
        #pragma unroll
        for (int k = 0; k < 2; k++) {
            int j4 = lane + 32 * k;
            float4 v = __ldg(rp4 + j4);
            int j = j4 * 4;
            s += seps[j]     ? EPSV : v.x;
            s += seps[j + 1] ? EPSV : v.y;
            s += seps[j + 2] ? EPSV : v.z;
            s += seps[j + 3] ? EPSV : v.w;
        }
        #pragma unroll
        for (int off = 16; off > 0; off >>= 1)
            s += __shfl_down_sync(0xffffffffu, s, off);
        if (lane == 0) rowsum[row] = s;
    }
    __syncthreads();

    __shared__ float bv[LHALF];
    __shared__ int   bix[LHALF];
    bv[tid]  = rowsum[tid];
    bix[tid] = tid;
    __syncthreads();
    for (int off = 128; off > 0; off >>= 1) {
        if (tid < off) {
            float vo = bv[tid + off];
            int   io = bix[tid + off];
            if (vo > bv[tid] || (vo == bv[tid] && io < bix[tid])) { bv[tid] = vo; bix[tid] = io; }
        }
        __syncthreads();
    }
    if (tid == 0) g_master[bh * 2 + half] = bix[0];
}

// ---------------- K2: gather windows -> slide (bf16 hi/lo) ----------------
__global__ void build_slide(const float* __restrict__ logits, const int* __restrict__ mask) {
    int bh = blockIdx.x;
    int b  = bh / HEADS;
    __shared__ int sa, sb;
    if (threadIdx.x == 0) {
        sa = window_start(g_master[bh * 2 + 0]);
        sb = window_start(g_master[bh * 2 + 1]);
    }
    __syncthreads();

    for (int idx = threadIdx.x; idx < TT * DIN; idx += blockDim.x) {
        int t = idx / DIN, f = idx % DIN;
        float v;
        if (f < DMODEL) {
            int row = sa + t;
            v = (mask[b * SEQ + row] == 0) ? EPSV
                : logits[((size_t)b * SEQ + row) * DMODEL + f];
        } else {
            int row = LHALF + sb + t;
            v = (mask[b * SEQ + row] == 0) ? EPSV
                : logits[((size_t)b * SEQ + row) * DMODEL + (f - DMODEL)];
        }
        size_t off = (size_t)bh * (TT * DIN) + idx;
        __nv_bfloat16 hi = __float2bfloat16(v);
        g_slide_h[off] = hi;
        g_slide_l[off] = __float2bfloat16(v - __bfloat162float(hi));
    }
}

// ---------------- K3: fused prep (all weight splits + bias) ----------------
#define NW ((size_t)G4 * DIN)    // 2359296
#define NH ((size_t)G4 * HH)     // 589824
#define PREP_TOTAL (2 * NW + 2 * NH + 2 * G4)

__global__ void prep_kernel(const float* __restrict__ wih_f, const float* __restrict__ wih_r,
                            const float* __restrict__ whh_f, const float* __restrict__ whh_r,
                            const float* __restrict__ bihf, const float* __restrict__ bhhf,
                            const float* __restrict__ bihr, const float* __restrict__ bhhr) {
    size_t i = (size_t)blockIdx.x * blockDim.x + threadIdx.x;
    if (i >= PREP_TOTAL) return;
    if (i < 2 * NW + 2 * NH) {
        const float* src;
        __nv_bfloat16 *dh, *dl;
        size_t off;
        if (i < NW)               { src = wih_f; dh = g_wih_h; dl = g_wih_l; off = i; }
        else if (i < 2 * NW)      { src = wih_r; dh = g_wih_h + NW; dl = g_wih_l + NW; off = i - NW; }
        else if (i < 2 * NW + NH) { src = whh_f; dh = g_whh_h; dl = g_whh_l; off = i - 2 * NW; }
        else                      { src = whh_r; dh = g_whh_h + NH; dl = g_whh_l + NH; off = i - 2 * NW - NH; }
        float x = src[off];
        __nv_bfloat16 hi = __float2bfloat16(x);
        dh[off] = hi;
        dl[off] = __float2bfloat16(x - __bfloat162float(hi));
    } else {
        size_t j = i - (2 * NW + 2 * NH);
        g_bias[j] = (j < G4) ? (bihf[j] + bhhf[j]) : (bihr[j - G4] + bhhr[j - G4]);
    }
}

// ---------------- K4: input HMMA GEMM (bf16 3-product split, fp32 accum) ----------------
// gatesX[2304][3072] = slide(2304x1536) @ [Wf;Wr](3072x1536)^T + bias
#define BK          64
#define CHUNK_BYTES 16384          // 128 rows x 128B (64 bf16)
#define BUF_BYTES   (4 * CHUNK_BYTES)
#define GM_SMEM     (1024 + 2 * BUF_BYTES)

// shared GEMM core: loads (Ah|Al|Bh|Bl) chunk, runs 3-product mainloop
__device__ __forceinline__ void gemm_core(
    const __nv_bfloat16* Ah, const __nv_bfloat16* Al,
    const __nv_bfloat16* Bh, const __nv_bfloat16* Bl,
    int bm, int bn, int K, int NC,
    char* smem_raw, uint32_t tiles_u,
    int tid, int wid, int lane, int wm, int wn,
    float acc[4][4][4])
{
    int Kd8 = K >> 3;
    const __nv_bfloat16* srcs[4] = {Ah, Al, Bh, Bl};
    int rows0[4] = {bm, bm, bn, bn};

    auto load_chunk = [&](int c, int buf) {
        int k0 = c * BK;
        uint32_t bufu = tiles_u + buf * BUF_BYTES;
        #pragma unroll
        for (int t4 = 0; t4 < 4; t4++) {
            const uint4* gp = (const uint4*)(srcs[t4] + (size_t)rows0[t4] * K + k0);
            uint32_t tb = bufu + t4 * CHUNK_BYTES;
            #pragma unroll
            for (int i = 0; i < 4; i++) {
                int u = tid + i * 256;
                int r = u >> 3, c16 = u & 7;
                const uint4* ga = gp + (size_t)r * Kd8 + c16;
                uint32_t off = (uint32_t)(r * 128 + c16 * 16);
                uint32_t sw = off ^ ((off >> 3) & 0x70);
                CP_ASYNC16(tb + sw, ga);
            }
        }
    };

    load_chunk(0, 0);
    CP_COMMIT();

    for (int c = 0; c < NC; c++) {
        CP_WAIT0();
        __syncthreads();
        if (c + 1 < NC) { load_chunk(c + 1, (c + 1) & 1); CP_COMMIT(); }

        uint32_t base = tiles_u + (c & 1) * BUF_BYTES;
        #pragma unroll
        for (int p = 0; p < 3; p++) {          // (Ah,Bh) (Ah,Bl) (Al,Bh)
            uint32_t abase = base + ((p == 2) ? CHUNK_BYTES : 0);
            uint32_t bbase = base + 2 * CHUNK_BYTES + ((p == 1) ? CHUNK_BYTES : 0);
            #pragma unroll
            for (int ks = 0; ks < 4; ks++) {
                uint32_t a[4][4];
                #pragma unroll
                for (int mt = 0; mt < 4; mt++) {
                    uint32_t r = wm + mt * 16 + (lane & 15);
                    uint32_t coloff = ks * 32 + ((lane >> 4) & 1) * 16;
                    uint32_t off = r * 128 + coloff;
                    uint32_t addr = abase + (off ^ ((off >> 3) & 0x70));
                    LDSM_X4(a[mt][0], a[mt][1], a[mt][2], a[mt][3], addr);
                }
                uint32_t b[4][2];
                #pragma unroll
                for (int h = 0; h < 2; h++) {
                    uint32_t r = wn + h * 16 + (lane & 7) + ((lane >> 4) << 3);
                    uint32_t coloff = ks * 32 + ((lane >> 3) & 1) * 16;
                    uint32_t off = r * 128 + coloff;
                    uint32_t addr = bbase + (off ^ ((off >> 3) & 0x70));
                    uint32_t r0, r1, r2, r3;
                    LDSM_X4(r0, r1, r2, r3, addr);
                    b[2 * h][0] = r0; b[2 * h][1] = r1;
                    b[2 * h + 1][0] = r2; b[2 * h + 1][1] = r3;
                }
                #pragma unroll
                for (int mt = 0; mt < 4; mt++)
                    #pragma unroll
                    for (int nt = 0; nt < 4; nt++)
                        MMA_BF16(acc[mt][nt][0], acc[mt][nt][1], acc[mt][nt][2], acc[mt][nt][3],
                                 a[mt][0], a[mt][1], a[mt][2], a[mt][3],
                                 b[nt][0], b[nt][1]);
            }
        }
        __syncthreads();
    }
}

__global__ __launch_bounds__(256, 1) void input_gemm_hmma() {
    extern __shared__ char smem_raw[];
    uint32_t smem_u = smem_u32(smem_raw);
    uint32_t tiles_u = (smem_u + 1023) & ~1023u;

    int tid = threadIdx.x, wid = tid >> 5, lane = tid & 31;
    int wm = (wid & 1) * 64, wn = (wid >> 1) * 32;
    int bm = blockIdx.y * 128;
    int bn = blockIdx.x * 128;

    float acc[4][4][4];
    #pragma unroll
    for (int i = 0; i < 4; i++)
        #pragma unroll
        for (int j = 0; j < 4; j++)
            #pragma unroll
            for (int q = 0; q < 4; q++) acc[i][j][q] = 0.0f;

    gemm_core(g_slide_h, g_slide_l, g_wih_h, g_wih_l,
              bm, bn, DIN, DIN / BK, smem_raw, tiles_u, tid, wid, lane, wm, wn, acc);

    #pragma unroll
    for (int mt = 0; mt < 4; mt++) {
        #pragma unroll
        for (int nt = 0; nt < 4; nt++) {
            int row = bm + wm + mt * 16 + (lane >> 2);
            int col = bn + wn + nt * 8 + (lane & 3) * 2;
            float b0 = g_bias[col], b1 = g_bias[col + 1];
            float2 v0 = make_float2(acc[mt][nt][0] + b0, acc[mt][nt][1] + b1);
            float2 v1 = make_float2(acc[mt][nt][2] + b0, acc[mt][nt][3] + b1);
            *(float2*)(g_gatesX + (size_t)row * (2 * G4) + col) = v0;
            *(float2*)(g_gatesX + (size_t)(row + 8) * (2 * G4) + col) = v1;
        }
    }
}

// ---------------- K5: persistent fused recurrence (all 6 steps, 1 launch) ----------------
#define NCTA_REC 72
#define REC_ELEMS (2 * BH * HH)            // 294912
#define REC_PER_THREAD (REC_ELEMS / (NCTA_REC * 256))   // 16

__device__ __forceinline__ void gsync() {
    __syncthreads();
    if (threadIdx.x == 0) {
        __threadfence();
        unsigned gen = *(volatile unsigned*)&g_bar_gen;
        if (atomicInc(&g_bar_cnt, NCTA_REC - 1) == NCTA_REC - 1) {
            atomicAdd(&g_bar_gen, 1u);
        } else {
            while (*(volatile unsigned*)&g_bar_gen == gen) {}
        }
        __threadfence();
    }
    __syncthreads();
}

__global__ __launch_bounds__(256, 1) void recurrence_kernel() {
    extern __shared__ char smem_raw[];
    uint32_t smem_u = smem_u32(smem_raw);
    uint32_t tiles_u = (smem_u + 1023) & ~1023u;

    int cta = blockIdx.x;
    int dir = cta / 36;
    int rem = cta % 36;
    int mt0 = rem / 12;                  // 0..2  (M tile of 384)
    int nt0 = rem % 12;                  // 0..11 (N tile of 1536)
    int bm = mt0 * 128, bn = nt0 * 128;

    int tid = threadIdx.x, wid = tid >> 5, lane = tid & 31;
    int wm = (wid & 1) * 64, wn = (wid >> 1) * 32;
    int gtid = cta * 256 + tid;

    const __nv_bfloat16* Ah = g_hb_h + (size_t)dir * BH * HH;
    const __nv_bfloat16* Al = g_hb_l + (size_t)dir * BH * HH;
    const __nv_bfloat16* Bh = g_whh_h + (size_t)dir * G4 * HH;
    const __nv_bfloat16* Bl = g_whh_l + (size_t)dir * G4 * HH;
    float* C = g_gtmp + (size_t)dir * BH * G4;

    float creg[REC_PER_THREAD];
    #pragma unroll
    for (int i = 0; i < REC_PER_THREAD; i++) creg[i] = 0.0f;

    for (int s = 0; s < TT; s++) {
        if (s > 0) {
            float acc[4][4][4];
            #pragma unroll
            for (int i = 0; i < 4; i++)
                #pragma unroll
                for (int j = 0; j < 4; j++)
                    #pragma unroll
                    for (int q = 0; q < 4; q++) acc[i][j][q] = 0.0f;

            gemm_core(Ah, Al, Bh, Bl, bm, bn, HH, HH / BK,
                      smem_raw, tiles_u, tid, wid, lane, wm, wn, acc);

            #pragma unroll
            for (int mt = 0; mt < 4; mt++) {
                #pragma unroll
                for (int nt = 0; nt < 4; nt++) {
                    int row = bm + wm + mt * 16 + (lane >> 2);
                    int col = bn + wn + nt * 8 + (lane & 3) * 2;
                    float2 v0 = make_float2(acc[mt][nt][0], acc[mt][nt][1]);
                    float2 v1 = make_float2(acc[mt][nt][2], acc[mt][nt][3]);
                    *(float2*)(C + (size_t)row * G4 + col) = v0;
                    *(float2*)(C + (size_t)(row + 8) * G4 + col) = v1;
                }
            }
            gsync();
        }

        // LSTM pointwise: 16 elems/thread, index map step-invariant -> c stays in regs
        #pragma unroll
        for (int i = 0; i < REC_PER_THREAD; i++) {
            int idx = gtid + i * (NCTA_REC * 256);
            int d2 = idx / (BH * HH);
            int r  = idx % (BH * HH);
            int n  = r / HH;
            int j  = r % HH;
            int t  = d2 ? (TT - 1 - s) : s;

            const float* G0 = g_gatesX + ((size_t)(n * TT + t)) * (2 * G4) + (size_t)d2 * G4;
            float gi = G0[j], gf = G0[HH + j], gg = G0[2 * HH + j], go = G0[3 * HH + j];
            if (s > 0) {
                const float* T0 = g_gtmp + (size_t)d2 * BH * G4 + (size_t)n * G4;
                gi += __ldcg(T0 + j);
                gf += __ldcg(T0 + HH + j);
                gg += __ldcg(T0 + 2 * HH + j);
                go += __ldcg(T0 + 3 * HH + j);
            }
            float c = sigf(gf) * creg[i] + sigf(gi) * tanhf(gg);
            float h = sigf(go) * tanhf(c);
            creg[i] = c;
            __nv_bfloat16 hi = __float2bfloat16(h);
            g_hb_h[idx] = hi;
            g_hb_l[idx] = __float2bfloat16(h - __bfloat162float(hi));
            g_compose[((size_t)n * TT + t) * DMODEL + d2 * HH + j] = h;
        }
        if (s < TT - 1) gsync();
    }
}

// ---------------- K7: logits_rep ----------------
__global__ void logits_rep_kernel(const float* __restrict__ logits, const int* __restrict__ mask) {
    int b = blockIdx.x;
    int tid = threadIdx.x;

    __shared__ unsigned char repl[SEQ];
    for (int i = tid; i < SEQ; i += blockDim.x) repl[i] = 0;
    __syncthreads();
    if (tid < 2 * HEADS) {
        int h = tid >> 1, half = tid & 1;
        int st = window_start(g_master[(b * HEADS + h) * 2 + half]);
        int base = half * LHALF + st;
        for (int k = 0; k < TT; k++) repl[base + k] = 1;
    }
    __syncthreads();
    for (int sPos = tid; sPos < SEQ; sPos += blockDim.x)
        repl[sPos] = (repl[sPos] && mask[b * SEQ + sPos] == 0) ? 1 : 0;
    __syncthreads();

    for (int d = tid; d < DMODEL; d += blockDim.x) {
        float a0 = 0.f, a1 = 0.f, a2 = 0.f, a3 = 0.f;
        const float* lp = logits + (size_t)b * SEQ * DMODEL + d;
        for (int sPos = 0; sPos < SEQ; sPos += 4) {
            float v0 = __ldg(lp + (size_t)(sPos + 0) * DMODEL);
            float v1 = __ldg(lp + (size_t)(sPos + 1) * DMODEL);
            float v2 = __ldg(lp + (size_t)(sPos + 2) * DMODEL);
            float v3 = __ldg(lp + (size_t)(sPos + 3) * DMODEL);
            a0 += repl[sPos]     ? EPSV : v0;
            a1 += repl[sPos + 1] ? EPSV : v1;
            a2 += repl[sPos + 2] ? EPSV : v2;
            a3 += repl[sPos + 3] ? EPSV : v3;
        }
        g_lrep[(size_t)b * DMODEL + d] = (a0 + a1 + a2 + a3) * (1.0f / (float)SEQ);
    }
}

// ---------------- K8: final FC + softmax ----------------
__global__ void final_kernel(const float* __restrict__ fcw, const float* __restrict__ fcb,
                             float* __restrict__ out) {
    int b = blockIdx.x;
    int tid = threadIdx.x;
    const int NF = DMODEL * (HEADS + 1);
    float a0 = 0.0f, a1 = 0.0f;

    for (int j = tid; j < NF; j += 256) {
        float x;
        if (j < HEADS * DMODEL) {
            int h = j / DMODEL, d = j % DMODEL;
            int n = b * HEADS + h;
            const float* cp = g_compose + (size_t)n * TT * DMODEL + d;
            float s = 0.0f;
            #pragma unroll
            for (int t = 0; t < TT; t++) s += cp[(size_t)t * DMODEL];
            x = s * (1.0f / (float)TT);
        } else {
            x = g_lrep[(size_t)b * DMODEL + (j - HEADS * DMODEL)];
        }
        a0 += x * fcw[j];
        a1 += x * fcw[NF + j];
    }

    __shared__ float s0[256], s1[256];
    s0[tid] = a0; s1[tid] = a1;
    __syncthreads();
    for (int off = 128; off > 0; off >>= 1) {
        if (tid < off) { s0[tid] += s0[tid + off]; s1[tid] += s1[tid + off]; }
        __syncthreads();
    }
    if (tid == 0) {
        float l0 = s0[0] + fcb[0], l1 = s1[0] + fcb[1];
        float m = fmaxf(l0, l1);
        float e0 = expf(l0 - m), e1 = expf(l1 - m);
        float inv = 1.0f / (e0 + e1);
        out[b * 2 + 0] = e0 * inv;
        out[b * 2 + 1] = e1 * inv;
    }
}

// ---------------- launch ----------------
extern "C" void kernel_launch(void* const* d_in, const int* in_sizes, int n_in,
                              void* d_out, int out_size) {
    const int*   sents = (const int*)d_in[0];
    const float* att   = (const float*)d_in[1];
    const float* logits= (const float*)d_in[2];
    const int*   mask  = (const int*)d_in[3];
    const float* wih_f = (const float*)d_in[4];
    const float* whh_f = (const float*)d_in[5];
    const float* bih_f = (const float*)d_in[6];
    const float* bhh_f = (const float*)d_in[7];
    const float* wih_r = (const float*)d_in[8];
    const float* whh_r = (const float*)d_in[9];
    const float* bih_r = (const float*)d_in[10];
    const float* bhh_r = (const float*)d_in[11];
    const float* fc_w  = (const float*)d_in[12];
    const float* fc_b  = (const float*)d_in[13];
    float* out = (float*)d_out;

    cudaFuncSetAttribute(input_gemm_hmma, cudaFuncAttributeMaxDynamicSharedMemorySize, GM_SMEM);
    cudaFuncSetAttribute(recurrence_kernel, cudaFuncAttributeMaxDynamicSharedMemorySize, GM_SMEM);

    prep_kernel<<<(int)((PREP_TOTAL + 255) / 256), 256>>>(wih_f, wih_r, whh_f, whh_r,
                                                          bih_f, bhh_f, bih_r, bhh_r);
    masters_kernel<<<BH * 2, 256>>>(att, sents);
    build_slide<<<BH, 256>>>(logits, mask);

    // input GEMM: gatesX(2304x3072) = slide @ [Wf;Wr]^T + bias
    input_gemm_hmma<<<dim3(2 * G4 / 128, BH * TT / 128), 256, GM_SMEM>>>();

    // fused BiLSTM recurrence: all 6 steps in one persistent launch
    recurrence_kernel<<<NCTA_REC, 256, GM_SMEM>>>();

    logits_rep_kernel<<<BATCH, 256>>>(logits, mask);
    final_kernel<<<BATCH, 256>>>(fc_w, fc_b, out);
}

// round 8
// speedup vs baseline: 1.1511x; 1.1511x over previous
#include <cuda_runtime.h>
#include <cuda_bf16.h>
#include <math.h>
#include <stdint.h>

// ---------------- problem constants ----------------
#define BATCH  32
#define HEADS  12
#define SEQ    512
#define LHALF  256
#define DMODEL 768
#define HH     384          // hidden per direction
#define G4     1536         // 4*HH gates
#define DIN    1536         // 2*DMODEL LSTM input
#define BH     384          // BATCH*HEADS
#define TT     6            // SLIDER
#define EPSV   1e-9f

// ---------------- device scratch (no allocs allowed) ----------------
__device__ int   g_master[BH * 2];
__device__ float g_gatesX[(size_t)BH * TT * 2 * G4];   // 2304 x 3072 (fwd | rev), bias folded
__device__ float g_gtmp[(size_t)2 * BH * G4];          // per-step h @ whh^T
__device__ float g_c[(size_t)2 * BH * HH];
__device__ float g_compose[(size_t)BH * TT * DMODEL];
__device__ float g_lrep[(size_t)BATCH * DMODEL];

// bf16 split operands
__device__ __nv_bfloat16 g_slide_h[(size_t)BH * TT * DIN];
__device__ __nv_bfloat16 g_slide_l[(size_t)BH * TT * DIN];
__device__ __nv_bfloat16 g_wih_h[(size_t)2 * G4 * DIN];   // [3072][1536]
__device__ __nv_bfloat16 g_wih_l[(size_t)2 * G4 * DIN];
__device__ __nv_bfloat16 g_whh_h[(size_t)2 * G4 * HH];    // [2][1536][384]
__device__ __nv_bfloat16 g_whh_l[(size_t)2 * G4 * HH];
__device__ __nv_bfloat16 g_hb_h[(size_t)2 * BH * HH];     // [2][384][384]
__device__ __nv_bfloat16 g_hb_l[(size_t)2 * BH * HH];
__device__ float g_bias[2 * G4];

// ---------------- PTX helpers (baseline PTX only) ----------------
__device__ __forceinline__ uint32_t smem_u32(const void* p) {
    uint32_t a;
    asm("{ .reg .u64 t; cvta.to.shared.u64 t, %1; cvt.u32.u64 %0, t; }" : "=r"(a) : "l"(p));
    return a;
}

#define CP_ASYNC16(sm, gm) \
    asm volatile("cp.async.cg.shared.global [%0], [%1], 16;" :: "r"(sm), "l"(gm) : "memory")
#define CP_COMMIT() asm volatile("cp.async.commit_group;" ::: "memory")
#define CP_WAIT0()  asm volatile("cp.async.wait_group 0;" ::: "memory")

#define LDSM_X4(r0, r1, r2, r3, addr) \
    asm volatile("ldmatrix.sync.aligned.m8n8.x4.shared.b16 {%0,%1,%2,%3}, [%4];" \
        : "=r"(r0), "=r"(r1), "=r"(r2), "=r"(r3) : "r"(addr))

#define MMA_BF16(c0, c1, c2, c3, a0, a1, a2, a3, b0, b1) \
    asm volatile("mma.sync.aligned.m16n8k16.row.col.f32.bf16.bf16.f32 " \
        "{%0,%1,%2,%3}, {%4,%5,%6,%7}, {%8,%9}, {%0,%1,%2,%3};" \
        : "+f"(c0), "+f"(c1), "+f"(c2), "+f"(c3) \
        : "r"(a0), "r"(a1), "r"(a2), "r"(a3), "r"(b0), "r"(b1))

// ---------------- helpers ----------------
__device__ __forceinline__ float sigf(float x) { return 1.0f / (1.0f + expf(-x)); }

__device__ __forceinline__ int window_start(int pos) {
    pos = min(max(pos, 1), LHALF - 2);
    int l = TT / 2;
    if (pos - TT / 2 <= 0) l = pos - 1;
    int r = TT - l;
    if (pos + r >= LHALF - 1) l = TT - (LHALF - pos - 2);
    return pos - l;
}

// ---------------- K1: masters ----------------
__global__ void masters_kernel(const float* __restrict__ att, const int* __restrict__ sents) {
    int bid  = blockIdx.x;
    int half = bid & 1;
    int bh   = bid >> 1;
    int b    = bh / HEADS;

    __shared__ unsigned char seps[LHALF];
    __shared__ float rowsum[LHALF];

    int tid = threadIdx.x;
    {
        int j = half * LHALF + tid;
        seps[tid] = (sents[b * SEQ + j] == 102) ? 1 : 0;
    }
    __syncthreads();

    const float* base = att + ((size_t)bh * SEQ + (size_t)half * LHALF) * SEQ + (size_t)half * LHALF;

    int warp = tid >> 5, lane = tid & 31;
    for (int row = warp; row < LHALF; row += 8) {
        const float4* rp4 = (const float4*)(base + (size_t)row * SEQ);
        float s = 0.0f;
        #pragma unroll
        for (int k = 0; k < 2; k++) {
            int j4 = lane + 32 * k;
            float4 v = __ldg(rp4 + j4);
            int j = j4 * 4;
            s += seps[j]     ? EPSV : v.x;
            s += seps[j + 1] ? EPSV : v.y;
            s += seps[j + 2] ? EPSV : v.z;
            s += seps[j + 3] ? EPSV : v.w;
        }
        #pragma unroll
        for (int off = 16; off > 0; off >>= 1)
            s += __shfl_down_sync(0xffffffffu, s, off);
        if (lane == 0) rowsum[row] = s;
    }
    __syncthreads();

    __shared__ float bv[LHALF];
    __shared__ int   bix[LHALF];
    bv[tid]  = rowsum[tid];
    bix[tid] = tid;
    __syncthreads();
    for (int off = 128; off > 0; off >>= 1) {
        if (tid < off) {
            float vo = bv[tid + off];
            int   io = bix[tid + off];
            if (vo > bv[tid] || (vo == bv[tid] && io < bix[tid])) { bv[tid] = vo; bix[tid] = io; }
        }
        __syncthreads();
    }
    if (tid == 0) g_master[bh * 2 + half] = bix[0];
}

// ---------------- K2: gather windows -> slide (bf16 hi/lo) ----------------
__global__ void build_slide(const float* __restrict__ logits, const int* __restrict__ mask) {
    int bh = blockIdx.x;
    int b  = bh / HEADS;
    __shared__ int sa, sb;
    if (threadIdx.x == 0) {
        sa = window_start(g_master[bh * 2 + 0]);
        sb = window_start(g_master[bh * 2 + 1]);
    }
    __syncthreads();

    for (int idx = threadIdx.x; idx < TT * DIN; idx += blockDim.x) {
        int t = idx / DIN, f = idx % DIN;
        float v;
        if (f < DMODEL) {
            int row = sa + t;
            v = (mask[b * SEQ + row] == 0) ? EPSV
                : logits[((size_t)b * SEQ + row) * DMODEL + f];
        } else {
            int row = LHALF + sb + t;
            v = (mask[b * SEQ + row] == 0) ? EPSV
                : logits[((size_t)b * SEQ + row) * DMODEL + (f - DMODEL)];
        }
        size_t off = (size_t)bh * (TT * DIN) + idx;
        __nv_bfloat16 hi = __float2bfloat16(v);
        g_slide_h[off] = hi;
        g_slide_l[off] = __float2bfloat16(v - __bfloat162float(hi));
    }
}

// ---------------- K3: fused prep (all weight splits + bias) ----------------
#define NW ((size_t)G4 * DIN)    // 2359296
#define NH ((size_t)G4 * HH)     // 589824
#define PREP_TOTAL (2 * NW + 2 * NH + 2 * G4)

__global__ void prep_kernel(const float* __restrict__ wih_f, const float* __restrict__ wih_r,
                            const float* __restrict__ whh_f, const float* __restrict__ whh_r,
                            const float* __restrict__ bihf, const float* __restrict__ bhhf,
                            const float* __restrict__ bihr, const float* __restrict__ bhhr) {
    size_t i = (size_t)blockIdx.x * blockDim.x + threadIdx.x;
    if (i >= PREP_TOTAL) return;
    if (i < 2 * NW + 2 * NH) {
        const float* src;
        __nv_bfloat16 *dh, *dl;
        size_t off;
        if (i < NW)               { src = wih_f; dh = g_wih_h; dl = g_wih_l; off = i; }
        else if (i < 2 * NW)      { src = wih_r; dh = g_wih_h + NW; dl = g_wih_l + NW; off = i - NW; }
        else if (i < 2 * NW + NH) { src = whh_f; dh = g_whh_h; dl = g_whh_l; off = i - 2 * NW; }
        else                      { src = whh_r; dh = g_whh_h + NH; dl = g_whh_l + NH; off = i - 2 * NW - NH; }
        float x = src[off];
        __nv_bfloat16 hi = __float2bfloat16(x);
        dh[off] = hi;
        dl[off] = __float2bfloat16(x - __bfloat162float(hi));
    } else {
        size_t j = i - (2 * NW + 2 * NH);
        g_bias[j] = (j < G4) ? (bihf[j] + bhhf[j]) : (bihr[j - G4] + bhhr[j - G4]);
    }
}

// ---------------- GEMM core (bf16 3-product split, fp32 accum) ----------------
// Fragments (Ah,Al,Bh,Bl) are loaded ONCE per k-step and reused across the
// three MMA product passes: Ah*Bh, Ah*Bl, Al*Bh.
#define BK          64
#define CHUNK_BYTES 16384          // 128 rows x 128B (64 bf16)
#define BUF_BYTES   (4 * CHUNK_BYTES)
#define GM_SMEM     (1024 + 2 * BUF_BYTES)

__device__ __forceinline__ void gemm_core(
    const __nv_bfloat16* Ah, const __nv_bfloat16* Al,
    const __nv_bfloat16* Bh, const __nv_bfloat16* Bl,
    int bm, int bn, int K, int NC,
    char* smem_raw, uint32_t tiles_u,
    int tid, int lane, int wm, int wn,
    float acc[4][4][4])
{
    int Kd8 = K >> 3;
    const __nv_bfloat16* srcs[4] = {Ah, Al, Bh, Bl};
    int rows0[4] = {bm, bm, bn, bn};

    auto load_chunk = [&](int c, int buf) {
        int k0 = c * BK;
        uint32_t bufu = tiles_u + buf * BUF_BYTES;
        #pragma unroll
        for (int t4 = 0; t4 < 4; t4++) {
            const uint4* gp = (const uint4*)(srcs[t4] + (size_t)rows0[t4] * K + k0);
            uint32_t tb = bufu + t4 * CHUNK_BYTES;
            #pragma unroll
            for (int i = 0; i < 4; i++) {
                int u = tid + i * 256;
                int r = u >> 3, c16 = u & 7;
                const uint4* ga = gp + (size_t)r * Kd8 + c16;
                uint32_t off = (uint32_t)(r * 128 + c16 * 16);
                uint32_t sw = off ^ ((off >> 3) & 0x70);
                CP_ASYNC16(tb + sw, ga);
            }
        }
    };

    load_chunk(0, 0);
    CP_COMMIT();

    for (int c = 0; c < NC; c++) {
        CP_WAIT0();
        __syncthreads();
        if (c + 1 < NC) { load_chunk(c + 1, (c + 1) & 1); CP_COMMIT(); }

        uint32_t base = tiles_u + (c & 1) * BUF_BYTES;
        uint32_t ah_base = base;
        uint32_t al_base = base + CHUNK_BYTES;
        uint32_t bh_base = base + 2 * CHUNK_BYTES;
        uint32_t bl_base = base + 3 * CHUNK_BYTES;

        #pragma unroll
        for (int ks = 0; ks < 4; ks++) {
            // ---- load all fragments once ----
            uint32_t a_h[4][4], a_l[4][4];
            #pragma unroll
            for (int mt = 0; mt < 4; mt++) {
                uint32_t r = wm + mt * 16 + (lane & 15);
                uint32_t coloff = ks * 32 + ((lane >> 4) & 1) * 16;
                uint32_t off = r * 128 + coloff;
                uint32_t sw = off ^ ((off >> 3) & 0x70);
                LDSM_X4(a_h[mt][0], a_h[mt][1], a_h[mt][2], a_h[mt][3], ah_base + sw);
                LDSM_X4(a_l[mt][0], a_l[mt][1], a_l[mt][2], a_l[mt][3], al_base + sw);
            }
            uint32_t b_h[4][2], b_l[4][2];
            #pragma unroll
            for (int h = 0; h < 2; h++) {
                uint32_t r = wn + h * 16 + (lane & 7) + ((lane >> 4) << 3);
                uint32_t coloff = ks * 32 + ((lane >> 3) & 1) * 16;
                uint32_t off = r * 128 + coloff;
                uint32_t sw = off ^ ((off >> 3) & 0x70);
                uint32_t r0, r1, r2, r3;
                LDSM_X4(r0, r1, r2, r3, bh_base + sw);
                b_h[2 * h][0] = r0; b_h[2 * h][1] = r1;
                b_h[2 * h + 1][0] = r2; b_h[2 * h + 1][1] = r3;
                LDSM_X4(r0, r1, r2, r3, bl_base + sw);
                b_l[2 * h][0] = r0; b_l[2 * h][1] = r1;
                b_l[2 * h + 1][0] = r2; b_l[2 * h + 1][1] = r3;
            }
            // ---- 3 product passes on registers ----
            #pragma unroll
            for (int mt = 0; mt < 4; mt++)
                #pragma unroll
                for (int nt = 0; nt < 4; nt++)
                    MMA_BF16(acc[mt][nt][0], acc[mt][nt][1], acc[mt][nt][2], acc[mt][nt][3],
                             a_h[mt][0], a_h[mt][1], a_h[mt][2], a_h[mt][3],
                             b_h[nt][0], b_h[nt][1]);
            #pragma unroll
            for (int mt = 0; mt < 4; mt++)
                #pragma unroll
                for (int nt = 0; nt < 4; nt++)
                    MMA_BF16(acc[mt][nt][0], acc[mt][nt][1], acc[mt][nt][2], acc[mt][nt][3],
                             a_h[mt][0], a_h[mt][1], a_h[mt][2], a_h[mt][3],
                             b_l[nt][0], b_l[nt][1]);
            #pragma unroll
            for (int mt = 0; mt < 4; mt++)
                #pragma unroll
                for (int nt = 0; nt < 4; nt++)
                    MMA_BF16(acc[mt][nt][0], acc[mt][nt][1], acc[mt][nt][2], acc[mt][nt][3],
                             a_l[mt][0], a_l[mt][1], a_l[mt][2], a_l[mt][3],
                             b_h[nt][0], b_h[nt][1]);
        }
        __syncthreads();
    }
}

// ---------------- K4: input GEMM ----------------
__global__ __launch_bounds__(256, 1) void input_gemm_hmma() {
    extern __shared__ char smem_raw[];
    uint32_t smem_u = smem_u32(smem_raw);
    uint32_t tiles_u = (smem_u + 1023) & ~1023u;

    int tid = threadIdx.x, wid = tid >> 5, lane = tid & 31;
    int wm = (wid & 1) * 64, wn = (wid >> 1) * 32;
    int bm = blockIdx.y * 128;
    int bn = blockIdx.x * 128;

    float acc[4][4][4];
    #pragma unroll
    for (int i = 0; i < 4; i++)
        #pragma unroll
        for (int j = 0; j < 4; j++)
            #pragma unroll
            for (int q = 0; q < 4; q++) acc[i][j][q] = 0.0f;

    gemm_core(g_slide_h, g_slide_l, g_wih_h, g_wih_l,
              bm, bn, DIN, DIN / BK, smem_raw, tiles_u, tid, lane, wm, wn, acc);

    #pragma unroll
    for (int mt = 0; mt < 4; mt++) {
        #pragma unroll
        for (int nt = 0; nt < 4; nt++) {
            int row = bm + wm + mt * 16 + (lane >> 2);
            int col = bn + wn + nt * 8 + (lane & 3) * 2;
            float b0 = g_bias[col], b1 = g_bias[col + 1];
            float2 v0 = make_float2(acc[mt][nt][0] + b0, acc[mt][nt][1] + b1);
            float2 v1 = make_float2(acc[mt][nt][2] + b0, acc[mt][nt][3] + b1);
            *(float2*)(g_gatesX + (size_t)row * (2 * G4) + col) = v0;
            *(float2*)(g_gatesX + (size_t)(row + 8) * (2 * G4) + col) = v1;
        }
    }
}

// ---------------- K5: recurrent GEMM  gtmp[dir] = h[dir] @ whh[dir]^T ----------------
__global__ __launch_bounds__(256, 1) void rec_gemm_hmma() {
    extern __shared__ char smem_raw[];
    uint32_t smem_u = smem_u32(smem_raw);
    uint32_t tiles_u = (smem_u + 1023) & ~1023u;

    int z = blockIdx.z;
    const __nv_bfloat16* Ah = g_hb_h + (size_t)z * BH * HH;
    const __nv_bfloat16* Al = g_hb_l + (size_t)z * BH * HH;
    const __nv_bfloat16* Bh = g_whh_h + (size_t)z * G4 * HH;
    const __nv_bfloat16* Bl = g_whh_l + (size_t)z * G4 * HH;
    float* C = g_gtmp + (size_t)z * BH * G4;

    int tid = threadIdx.x, wid = tid >> 5, lane = tid & 31;
    int wm = (wid & 1) * 64, wn = (wid >> 1) * 32;
    int bm = blockIdx.y * 128;
    int bn = blockIdx.x * 128;

    float acc[4][4][4];
    #pragma unroll
    for (int i = 0; i < 4; i++)
        #pragma unroll
        for (int j = 0; j < 4; j++)
            #pragma unroll
            for (int q = 0; q < 4; q++) acc[i][j][q] = 0.0f;

    gemm_core(Ah, Al, Bh, Bl, bm, bn, HH, HH / BK,
              smem_raw, tiles_u, tid, lane, wm, wn, acc);

    #pragma unroll
    for (int mt = 0; mt < 4; mt++) {
        #pragma unroll
        for (int nt = 0; nt < 4; nt++) {
            int row = bm + wm + mt * 16 + (lane >> 2);
            int col = bn + wn + nt * 8 + (lane & 3) * 2;
            float2 v0 = make_float2(acc[mt][nt][0], acc[mt][nt][1]);
            float2 v1 = make_float2(acc[mt][nt][2], acc[mt][nt][3]);
            *(float2*)(C + (size_t)row * G4 + col) = v0;
            *(float2*)(C + (size_t)(row + 8) * G4 + col) = v1;
        }
    }
}

// ---------------- K6: per-step LSTM pointwise ----------------
__global__ void lstm_point(int s) {
    int idx = blockIdx.x * blockDim.x + threadIdx.x;
    if (idx >= 2 * BH * HH) return;
    int dir = idx / (BH * HH);
    int r   = idx % (BH * HH);
    int n   = r / HH;
    int j   = r % HH;
    int t   = dir ? (TT - 1 - s) : s;

    const float* G0 = g_gatesX + ((size_t)(n * TT + t)) * (2 * G4) + (size_t)dir * G4;
    float gi = G0[j], gf = G0[HH + j], gg = G0[2 * HH + j], go = G0[3 * HH + j];

    float c;
    if (s == 0) {
        // h0 = c0 = 0 -> no gtmp term, no c_prev term
        c = sigf(gi) * tanhf(gg);
    } else {
        const float* T0 = g_gtmp + (size_t)dir * BH * G4 + (size_t)n * G4;
        gi += T0[j];
        gf += T0[HH + j];
        gg += T0[2 * HH + j];
        go += T0[3 * HH + j];
        c = sigf(gf) * g_c[idx] + sigf(gi) * tanhf(gg);
    }
    float h = sigf(go) * tanhf(c);
    g_c[idx] = c;
    __nv_bfloat16 hi = __float2bfloat16(h);
    g_hb_h[idx] = hi;
    g_hb_l[idx] = __float2bfloat16(h - __bfloat162float(hi));
    g_compose[((size_t)n * TT + t) * DMODEL + dir * HH + j] = h;
}

// ---------------- K7: logits_rep ----------------
__global__ void logits_rep_kernel(const float* __restrict__ logits, const int* __restrict__ mask) {
    int b = blockIdx.x;
    int tid = threadIdx.x;

    __shared__ unsigned char repl[SEQ];
    for (int i = tid; i < SEQ; i += blockDim.x) repl[i] = 0;
    __syncthreads();
    if (tid < 2 * HEADS) {
        int h = tid >> 1, half = tid & 1;
        int st = window_start(g_master[(b * HEADS + h) * 2 + half]);
        int base = half * LHALF + st;
        for (int k = 0; k < TT; k++) repl[base + k] = 1;
    }
    __syncthreads();
    for (int sPos = tid; sPos < SEQ; sPos += blockDim.x)
        repl[sPos] = (repl[sPos] && mask[b * SEQ + sPos] == 0) ? 1 : 0;
    __syncthreads();

    for (int d = tid; d < DMODEL; d += blockDim.x) {
        float a0 = 0.f, a1 = 0.f, a2 = 0.f, a3 = 0.f;
        const float* lp = logits + (size_t)b * SEQ * DMODEL + d;
        for (int sPos = 0; sPos < SEQ; sPos += 4) {
            float v0 = __ldg(lp + (size_t)(sPos + 0) * DMODEL);
            float v1 = __ldg(lp + (size_t)(sPos + 1) * DMODEL);
            float v2 = __ldg(lp + (size_t)(sPos + 2) * DMODEL);
            float v3 = __ldg(lp + (size_t)(sPos + 3) * DMODEL);
            a0 += repl[sPos]     ? EPSV : v0;
            a1 += repl[sPos + 1] ? EPSV : v1;
            a2 += repl[sPos + 2] ? EPSV : v2;
            a3 += repl[sPos + 3] ? EPSV : v3;
        }
        g_lrep[(size_t)b * DMODEL + d] = (a0 + a1 + a2 + a3) * (1.0f / (float)SEQ);
    }
}

// ---------------- K8: final FC + softmax ----------------
__global__ void final_kernel(const float* __restrict__ fcw, const float* __restrict__ fcb,
                             float* __restrict__ out) {
    int b = blockIdx.x;
    int tid = threadIdx.x;
    const int NF = DMODEL * (HEADS + 1);
    float a0 = 0.0f, a1 = 0.0f;

    for (int j = tid; j < NF; j += 256) {
        float x;
        if (j < HEADS * DMODEL) {
            int h = j / DMODEL, d = j % DMODEL;
            int n = b * HEADS + h;
            const float* cp = g_compose + (size_t)n * TT * DMODEL + d;
            float s = 0.0f;
            #pragma unroll
            for (int t = 0; t < TT; t++) s += cp[(size_t)t * DMODEL];
            x = s * (1.0f / (float)TT);
        } else {
            x = g_lrep[(size_t)b * DMODEL + (j - HEADS * DMODEL)];
        }
        a0 += x * fcw[j];
        a1 += x * fcw[NF + j];
    }

    __shared__ float s0[256], s1[256];
    s0[tid] = a0; s1[tid] = a1;
    __syncthreads();
    for (int off = 128; off > 0; off >>= 1) {
        if (tid < off) { s0[tid] += s0[tid + off]; s1[tid] += s1[tid + off]; }
        __syncthreads();
    }
    if (tid == 0) {
        float l0 = s0[0] + fcb[0], l1 = s1[0] + fcb[1];
        float m = fmaxf(l0, l1);
        float e0 = expf(l0 - m), e1 = expf(l1 - m);
        float inv = 1.0f / (e0 + e1);
        out[b * 2 + 0] = e0 * inv;
        out[b * 2 + 1] = e1 * inv;
    }
}

// ---------------- launch ----------------
extern "C" void kernel_launch(void* const* d_in, const int* in_sizes, int n_in,
                              void* d_out, int out_size) {
    const int*   sents = (const int*)d_in[0];
    const float* att   = (const float*)d_in[1];
    const float* logits= (const float*)d_in[2];
    const int*   mask  = (const int*)d_in[3];
    const float* wih_f = (const float*)d_in[4];
    const float* whh_f = (const float*)d_in[5];
    const float* bih_f = (const float*)d_in[6];
    const float* bhh_f = (const float*)d_in[7];
    const float* wih_r = (const float*)d_in[8];
    const float* whh_r = (const float*)d_in[9];
    const float* bih_r = (const float*)d_in[10];
    const float* bhh_r = (const float*)d_in[11];
    const float* fc_w  = (const float*)d_in[12];
    const float* fc_b  = (const float*)d_in[13];
    float* out = (float*)d_out;

    cudaFuncSetAttribute(input_gemm_hmma, cudaFuncAttributeMaxDynamicSharedMemorySize, GM_SMEM);
    cudaFuncSetAttribute(rec_gemm_hmma, cudaFuncAttributeMaxDynamicSharedMemorySize, GM_SMEM);

    prep_kernel<<<(int)((PREP_TOTAL + 255) / 256), 256>>>(wih_f, wih_r, whh_f, whh_r,
                                                          bih_f, bhh_f, bih_r, bhh_r);
    masters_kernel<<<BH * 2, 256>>>(att, sents);
    build_slide<<<BH, 256>>>(logits, mask);

    // input GEMM: gatesX(2304x3072) = slide @ [Wf;Wr]^T + bias
    input_gemm_hmma<<<dim3(2 * G4 / 128, BH * TT / 128), 256, GM_SMEM>>>();

    for (int s = 0; s < TT; s++) {
        lstm_point<<<(2 * BH * HH + 255) / 256, 256>>>(s);
        if (s < TT - 1) {
            rec_gemm_hmma<<<dim3(G4 / 128, BH / 128, 2), 256, GM_SMEM>>>();
        }
    }

    logits_rep_kernel<<<BATCH, 256>>>(logits, mask);
    final_kernel<<<BATCH, 256>>>(fc_w, fc_b, out);
}